// round 1
// baseline (speedup 1.0000x reference)
#include <cuda_runtime.h>
#include <math.h>

#define BATCH  2
#define SEQ    1024
#define DMODEL 1024
#define DINNER 2048
#define DSTATE 16
#define NROWS  (BATCH*SEQ)      // 2048
#define DBCN   96               // DT_RANK + 2*D_STATE
#define XZN    (2*DINNER)       // 4096

// ---------------- scratch (static device globals; no allocations) ----------
__device__ float g_xrev[(size_t)NROWS*DMODEL];
__device__ float g_xz  [2][(size_t)NROWS*XZN];
__device__ float g_xi  [2][(size_t)NROWS*DINNER];
__device__ float g_dbc [2][(size_t)NROWS*DBCN];
__device__ float g_dt  [2][(size_t)NROWS*DINNER];
__device__ float g_y   [2][(size_t)NROWS*DINNER];
__device__ float g_outd[2][(size_t)NROWS*DMODEL];
__device__ float g_A   [2][DINNER*DSTATE];
__device__ int   g_fastA[2];

// ---------------- reverse x along sequence --------------------------------
__global__ void reverse_kernel(const float* __restrict__ x) {
    int idx = blockIdx.x * blockDim.x + threadIdx.x;
    if (idx >= NROWS * DMODEL) return;
    int c = idx % DMODEL;
    int row = idx / DMODEL;
    int b = row / SEQ, l = row % SEQ;
    g_xrev[(size_t)(b*SEQ + (SEQ-1-l))*DMODEL + c] = x[idx];
}

// ---------------- precompute A = -exp(A_log); detect A_s == -(s+1) --------
__global__ void prepA_kernel(const float* __restrict__ Alog0,
                             const float* __restrict__ Alog1) {
    int dir = blockIdx.x;
    const float* Alog = dir ? Alog1 : Alog0;
    __shared__ int ok;
    if (threadIdx.x == 0) ok = 1;
    __syncthreads();
    bool good = true;
    for (int i = threadIdx.x; i < DINNER*DSTATE; i += blockDim.x) {
        float a = -__expf(Alog[i]);
        g_A[dir][i] = a;
        int s = i & (DSTATE-1);
        if (fabsf(a + (float)(s+1)) > 1e-3f * (float)(s+1)) good = false;
    }
    if (!good) atomicExch(&ok, 0);
    __syncthreads();
    if (threadIdx.x == 0) g_fastA[dir] = ok;
}

// ---------------- generic tiled fp32 GEMM: C = A(M,K) * W(N,K)^T ----------
// EPI: 0 = none, 1 = softplus(v + bias[n]), 2 = sigmoid(v)
// blockIdx.z selects the direction's pointer set (both dirs in one launch).
#define BM 128
#define BN 128
#define BK 8

template<int EPI>
__global__ __launch_bounds__(256)
void gemm_kernel(const float* __restrict__ A0, const float* __restrict__ A1,
                 const float* __restrict__ W0, const float* __restrict__ W1,
                 const float* __restrict__ b0, const float* __restrict__ b1,
                 float* __restrict__ C0, float* __restrict__ C1,
                 int M, int N, int K, int lda) {
    const float* A = blockIdx.z ? A1 : A0;
    const float* W = blockIdx.z ? W1 : W0;
    const float* bias = blockIdx.z ? b1 : b0;
    float* C = blockIdx.z ? C1 : C0;

    __shared__ float As[BK][BM+4];
    __shared__ float Ws[BK][BN+4];

    int tid = threadIdx.x;
    int m0 = blockIdx.y * BM;
    int n0 = blockIdx.x * BN;
    int lr = tid >> 1;            // 0..127 (tile row)
    int lc = (tid & 1) * 4;       // 0 or 4 (k offset)
    int tx = tid & 15, ty = tid >> 4;

    float acc[8][8];
    #pragma unroll
    for (int i = 0; i < 8; i++)
        #pragma unroll
        for (int j = 0; j < 8; j++) acc[i][j] = 0.f;

    for (int k0 = 0; k0 < K; k0 += BK) {
        float4 av = make_float4(0.f,0.f,0.f,0.f);
        float4 wv = make_float4(0.f,0.f,0.f,0.f);
        int am = m0 + lr;
        if (am < M) av = *(const float4*)(A + (size_t)am*lda + k0 + lc);
        int wn = n0 + lr;
        if (wn < N) wv = *(const float4*)(W + (size_t)wn*K + k0 + lc);
        __syncthreads();
        As[lc+0][lr] = av.x; As[lc+1][lr] = av.y;
        As[lc+2][lr] = av.z; As[lc+3][lr] = av.w;
        Ws[lc+0][lr] = wv.x; Ws[lc+1][lr] = wv.y;
        Ws[lc+2][lr] = wv.z; Ws[lc+3][lr] = wv.w;
        __syncthreads();
        #pragma unroll
        for (int k = 0; k < BK; k++) {
            float a[8], b[8];
            #pragma unroll
            for (int i = 0; i < 8; i++) a[i] = As[k][ty*8+i];
            #pragma unroll
            for (int j = 0; j < 8; j++) b[j] = Ws[k][tx*8+j];
            #pragma unroll
            for (int i = 0; i < 8; i++)
                #pragma unroll
                for (int j = 0; j < 8; j++)
                    acc[i][j] = fmaf(a[i], b[j], acc[i][j]);
        }
    }

    #pragma unroll
    for (int i = 0; i < 8; i++) {
        int m = m0 + ty*8 + i;
        if (m >= M) continue;
        #pragma unroll
        for (int j = 0; j < 8; j++) {
            int n = n0 + tx*8 + j;
            if (n >= N) continue;
            float v = acc[i][j];
            if (EPI == 1) {               // softplus(v + bias)
                v += bias[n];
                v = (v > 20.f) ? v : log1pf(__expf(v));
            } else if (EPI == 2) {        // sigmoid
                v = 1.f / (1.f + __expf(-v));
            }
            C[(size_t)m*N + n] = v;
        }
    }
}

// ---------------- causal depthwise conv (k=4) + SiLU -----------------------
__global__ void conv_silu_kernel(const float* __restrict__ w0, const float* __restrict__ w1,
                                 const float* __restrict__ cb0, const float* __restrict__ cb1) {
    int dir = blockIdx.z;
    const float* w  = dir ? w1 : w0;
    const float* cb = dir ? cb1 : cb0;
    int idx = blockIdx.x * blockDim.x + threadIdx.x;
    if (idx >= NROWS * DINNER) return;
    int ch = idx % DINNER;
    int row = idx / DINNER;
    int l = row & (SEQ-1);
    const float* base = g_xz[dir] + (size_t)row*XZN + ch;
    float4 wv = ((const float4*)w)[ch];
    float acc = cb[ch];
    if (l >= 3) acc = fmaf(wv.x, base[-3*XZN], acc);
    if (l >= 2) acc = fmaf(wv.y, base[-2*XZN], acc);
    if (l >= 1) acc = fmaf(wv.z, base[-1*XZN], acc);
    acc = fmaf(wv.w, base[0], acc);
    g_xi[dir][idx] = acc / (1.f + __expf(-acc));   // SiLU
}

// ---------------- selective scan (fused with gate + D skip) ----------------
// one thread per channel d; 16 states in registers; B/C broadcast via shfl.
__global__ __launch_bounds__(256)
void scan_kernel(const float* __restrict__ D0, const float* __restrict__ D1) {
    int dir = blockIdx.z;
    const float* Dp = dir ? D1 : D0;
    int d = blockIdx.x * blockDim.x + threadIdx.x;
    int b = blockIdx.y;
    int lane = threadIdx.x & 31;

    const float* dtp = g_dt[dir]  + (size_t)b*SEQ*DINNER + d;
    const float* xip = g_xi[dir]  + (size_t)b*SEQ*DINNER + d;
    const float* zp  = g_xz[dir]  + (size_t)b*SEQ*XZN + DINNER + d;
    const float* vp  = g_dbc[dir] + (size_t)b*SEQ*DBCN + 64 + lane;
    float* yp        = g_y[dir]   + (size_t)b*SEQ*DINNER + d;

    float h[DSTATE];
    #pragma unroll
    for (int s = 0; s < DSTATE; s++) h[s] = 0.f;
    float Av[DSTATE];
    #pragma unroll
    for (int s = 0; s < DSTATE; s++) Av[s] = g_A[dir][d*DSTATE + s];
    float Dv = Dp[d];
    int fast = g_fastA[dir];

    #pragma unroll 1
    for (int l0 = 0; l0 < SEQ; l0 += 4) {
        float cdt[4], cxi[4], cz[4], cv[4];
        #pragma unroll
        for (int u = 0; u < 4; u++) {
            int r = l0 + u;
            cdt[u] = dtp[(size_t)r*DINNER];
            cxi[u] = xip[(size_t)r*DINNER];
            cz[u]  = zp [(size_t)r*XZN];
            cv[u]  = vp [(size_t)r*DBCN];
        }
        #pragma unroll
        for (int u = 0; u < 4; u++) {
            float dt = cdt[u], xi = cxi[u], z = cz[u], v = cv[u];
            float dtxi = dt * xi;
            float acc = 0.f;
            if (fast) {
                // A_s == -(s+1): dA_s = (e^{-dt})^{s+1} — one MUFU per (l,d)
                float e = __expf(-dt);
                float p = 1.f;
                #pragma unroll
                for (int s = 0; s < DSTATE; s++) {
                    p *= e;
                    float bs = __shfl_sync(0xffffffffu, v, s);
                    float cs = __shfl_sync(0xffffffffu, v, 16 + s);
                    h[s] = fmaf(p, h[s], dtxi * bs);
                    acc = fmaf(h[s], cs, acc);
                }
            } else {
                #pragma unroll
                for (int s = 0; s < DSTATE; s++) {
                    float a = __expf(dt * Av[s]);
                    float bs = __shfl_sync(0xffffffffu, v, s);
                    float cs = __shfl_sync(0xffffffffu, v, 16 + s);
                    h[s] = fmaf(a, h[s], dtxi * bs);
                    acc = fmaf(h[s], cs, acc);
                }
            }
            float sz = z / (1.f + __expf(-z));     // silu(z)
            yp[(size_t)(l0+u)*DINNER] = (acc + xi * Dv) * sz;
        }
    }
}

// ---------------- combine dirs + LayerNorm + residual ----------------------
__global__ __launch_bounds__(256)
void combine_ln_kernel(const float* __restrict__ x,
                       const float* __restrict__ lng, const float* __restrict__ lnb,
                       float* __restrict__ out) {
    int row = blockIdx.x;            // 0..2047
    int b = row / SEQ, l = row % SEQ;
    const float* f  = g_outd[0] + (size_t)row*DMODEL;
    const float* bk = g_outd[1] + (size_t)(b*SEQ + (SEQ-1-l))*DMODEL;
    int tid = threadIdx.x;

    float vals[4];
    float s = 0.f, s2 = 0.f;
    #pragma unroll
    for (int j = 0; j < 4; j++) {
        int i = tid + j*256;
        float dv = 0.5f * (f[i] + bk[i]);
        vals[j] = dv;
        s += dv; s2 += dv*dv;
    }
    #pragma unroll
    for (int o = 16; o; o >>= 1) {
        s  += __shfl_xor_sync(0xffffffffu, s,  o);
        s2 += __shfl_xor_sync(0xffffffffu, s2, o);
    }
    __shared__ float sh[2][8];
    if ((tid & 31) == 0) { sh[0][tid>>5] = s; sh[1][tid>>5] = s2; }
    __syncthreads();
    if (tid < 32) {
        float a  = (tid < 8) ? sh[0][tid] : 0.f;
        float a2 = (tid < 8) ? sh[1][tid] : 0.f;
        #pragma unroll
        for (int o = 4; o; o >>= 1) {
            a  += __shfl_xor_sync(0xffffffffu, a,  o);
            a2 += __shfl_xor_sync(0xffffffffu, a2, o);
        }
        if (tid == 0) { sh[0][0] = a; sh[1][0] = a2; }
    }
    __syncthreads();
    float mu  = sh[0][0] * (1.f/DMODEL);
    float var = sh[1][0] * (1.f/DMODEL) - mu*mu;
    float rstd = rsqrtf(var + 1e-5f);
    #pragma unroll
    for (int j = 0; j < 4; j++) {
        int i = tid + j*256;
        out[(size_t)row*DMODEL + i] =
            (vals[j] - mu) * rstd * lng[i] + lnb[i] + x[(size_t)row*DMODEL + i];
    }
}

// ---------------- host launcher --------------------------------------------
extern "C" void kernel_launch(void* const* d_in, const int* in_sizes, int n_in,
                              void* d_out, int out_size) {
    (void)in_sizes; (void)n_in; (void)out_size;
    const float* x       = (const float*)d_in[0];
    const float* Win[2]  = {(const float*)d_in[1],  (const float*)d_in[10]};
    const float* cw[2]   = {(const float*)d_in[2],  (const float*)d_in[11]};
    const float* cbv[2]  = {(const float*)d_in[3],  (const float*)d_in[12]};
    const float* xproj[2]= {(const float*)d_in[4],  (const float*)d_in[13]};
    const float* dtw[2]  = {(const float*)d_in[5],  (const float*)d_in[14]};
    const float* dtb[2]  = {(const float*)d_in[6],  (const float*)d_in[15]};
    const float* Alog[2] = {(const float*)d_in[7],  (const float*)d_in[16]};
    const float* Dp[2]   = {(const float*)d_in[8],  (const float*)d_in[17]};
    const float* Wout[2] = {(const float*)d_in[9],  (const float*)d_in[18]};
    const float* lng = (const float*)d_in[19];
    const float* lnb = (const float*)d_in[20];
    float* out = (float*)d_out;

    float *p_xrev, *p_xz, *p_xi, *p_dbc, *p_dt, *p_y, *p_out;
    cudaGetSymbolAddress((void**)&p_xrev, g_xrev);
    cudaGetSymbolAddress((void**)&p_xz,   g_xz);
    cudaGetSymbolAddress((void**)&p_xi,   g_xi);
    cudaGetSymbolAddress((void**)&p_dbc,  g_dbc);
    cudaGetSymbolAddress((void**)&p_dt,   g_dt);
    cudaGetSymbolAddress((void**)&p_y,    g_y);
    cudaGetSymbolAddress((void**)&p_out,  g_outd);

    const size_t sXZ  = (size_t)NROWS*XZN;
    const size_t sIN  = (size_t)NROWS*DINNER;
    const size_t sDBC = (size_t)NROWS*DBCN;
    const size_t sMD  = (size_t)NROWS*DMODEL;

    reverse_kernel<<<(NROWS*DMODEL + 255)/256, 256>>>(x);
    prepA_kernel<<<2, 256>>>(Alog[0], Alog[1]);

    // in_proj: xz = x @ Win^T   (M=2048, N=4096, K=1024)
    gemm_kernel<0><<<dim3(XZN/BN, NROWS/BM, 2), 256>>>(
        x, p_xrev, Win[0], Win[1], nullptr, nullptr,
        p_xz, p_xz + sXZ, NROWS, XZN, DMODEL, DMODEL);

    // conv + silu
    conv_silu_kernel<<<dim3((NROWS*DINNER + 255)/256, 1, 2), 256>>>(
        cw[0], cw[1], cbv[0], cbv[1]);

    // x_proj: dbc = xi @ xproj^T   (M=2048, N=96, K=2048)
    gemm_kernel<0><<<dim3(1, NROWS/BM, 2), 256>>>(
        p_xi, p_xi + sIN, xproj[0], xproj[1], nullptr, nullptr,
        p_dbc, p_dbc + sDBC, NROWS, DBCN, DINNER, DINNER);

    // dt = softplus(dbc[:, :64] @ dtw^T + dtb)   (M=2048, N=2048, K=64, lda=96)
    gemm_kernel<1><<<dim3(DINNER/BN, NROWS/BM, 2), 256>>>(
        p_dbc, p_dbc + sDBC, dtw[0], dtw[1], dtb[0], dtb[1],
        p_dt, p_dt + sIN, NROWS, DINNER, 64, DBCN);

    // selective scan + gating -> y
    scan_kernel<<<dim3(DINNER/256, BATCH, 2), 256>>>(Dp[0], Dp[1]);

    // out = sigmoid(y @ Wout^T)   (M=2048, N=1024, K=2048)
    gemm_kernel<2><<<dim3(DMODEL/BN, NROWS/BM, 2), 256>>>(
        p_y, p_y + sIN, Wout[0], Wout[1], nullptr, nullptr,
        p_out, p_out + sMD, NROWS, DMODEL, DINNER, DINNER);

    // combine + LN + residual
    combine_ln_kernel<<<NROWS, 256>>>(x, lng, lnb, out);
}

// round 2
// speedup vs baseline: 2.1307x; 2.1307x over previous
#include <cuda_runtime.h>
#include <math.h>
#include <stdint.h>

#define BATCH  2
#define SEQ    1024
#define DMODEL 1024
#define DINNER 2048
#define DSTATE 16
#define NROWS  (BATCH*SEQ)      // 2048
#define DBCN   96               // DT_RANK + 2*D_STATE
#define XZN    (2*DINNER)       // 4096

// ---------------- scratch (static device globals; no allocations) ----------
__device__ float g_xrev[(size_t)NROWS*DMODEL];
__device__ float g_xz  [2][(size_t)NROWS*XZN];
__device__ float g_xi  [2][(size_t)NROWS*DINNER];
__device__ float g_dbc [2][(size_t)NROWS*DBCN];
__device__ float g_dt  [2][(size_t)NROWS*DINNER];
__device__ float g_y   [2][(size_t)NROWS*DINNER];
__device__ float g_outd[2][(size_t)NROWS*DMODEL];
__device__ float g_A   [2][DINNER*DSTATE];
__device__ int   g_fastA[2];

// ---------------- reverse x along sequence --------------------------------
__global__ void reverse_kernel(const float* __restrict__ x) {
    int idx = blockIdx.x * blockDim.x + threadIdx.x;
    if (idx >= NROWS * DMODEL) return;
    int c = idx % DMODEL;
    int row = idx / DMODEL;
    int b = row / SEQ, l = row % SEQ;
    g_xrev[(size_t)(b*SEQ + (SEQ-1-l))*DMODEL + c] = x[idx];
}

// ---------------- precompute A = -exp(A_log); detect A_s == -(s+1) --------
__global__ void prepA_kernel(const float* __restrict__ Alog0,
                             const float* __restrict__ Alog1) {
    int dir = blockIdx.x;
    const float* Alog = dir ? Alog1 : Alog0;
    __shared__ int ok;
    if (threadIdx.x == 0) ok = 1;
    __syncthreads();
    bool good = true;
    for (int i = threadIdx.x; i < DINNER*DSTATE; i += blockDim.x) {
        float a = -__expf(Alog[i]);
        g_A[dir][i] = a;
        int s = i & (DSTATE-1);
        if (fabsf(a + (float)(s+1)) > 1e-3f * (float)(s+1)) good = false;
    }
    if (!good) atomicExch(&ok, 0);
    __syncthreads();
    if (threadIdx.x == 0) g_fastA[dir] = ok;
}

// =====================  TF32 tensor-core GEMM  ==============================
// C(M,N) = A(M,K; lda) * W(N,K)^T   both K-major.
// Block tile 128x128, BK=16, 256 threads (8 warps, each 64x32).
// SMEM layout conflict-free for STS.128 and fragment LDS.32:
//   f(row,k) = row*16 + 4*((k>>2) ^ ((row>>1)&3)) + (k&3)
// EPI: 0 none, 1 softplus(v+bias[n]), 2 sigmoid(v)

__device__ __forceinline__ uint32_t f2tf32(float f) {
    uint32_t r;
    asm("cvt.rna.tf32.f32 %0, %1;" : "=r"(r) : "f"(f));
    return r;
}
__device__ __forceinline__ int swz_idx(int row, int k) {
    return row*16 + 4*((k>>2) ^ ((row>>1)&3)) + (k&3);
}

template<int EPI>
__global__ __launch_bounds__(256)
void mma_gemm(const float* __restrict__ A0, const float* __restrict__ A1,
              const float* __restrict__ W0, const float* __restrict__ W1,
              const float* __restrict__ b0, const float* __restrict__ b1,
              float* __restrict__ C0, float* __restrict__ C1,
              int M, int N, int K, int lda) {
    const float* A = blockIdx.z ? A1 : A0;
    const float* W = blockIdx.z ? W1 : W0;
    const float* bias = blockIdx.z ? b1 : b0;
    float* C = blockIdx.z ? C1 : C0;

    __shared__ uint32_t As[2][128*16];
    __shared__ uint32_t Ws[2][128*16];

    const int tid  = threadIdx.x;
    const int lane = tid & 31;
    const int wid  = tid >> 5;
    const int warp_m = (wid & 1) * 64;
    const int warp_n = (wid >> 1) * 32;
    const int m0 = blockIdx.y * 128;
    const int n0 = blockIdx.x * 128;

    // loader mapping: each thread loads 2 rows of A tile + 2 rows of W tile
    const int lm  = tid >> 2;        // 0..63
    const int lkc = tid & 3;         // float4 k-chunk

    float acc[4][4][4];
    #pragma unroll
    for (int i = 0; i < 4; i++)
        #pragma unroll
        for (int j = 0; j < 4; j++)
            #pragma unroll
            for (int r = 0; r < 4; r++) acc[i][j][r] = 0.f;

    float4 av[2], wv[2];
    auto ld_tile = [&](int k0) {
        #pragma unroll
        for (int r = 0; r < 2; r++) {
            int row = lm + 64*r;
            av[r] = *(const float4*)(A + (size_t)(m0+row)*lda + k0 + 4*lkc);
            if (n0 + row < N)
                wv[r] = *(const float4*)(W + (size_t)(n0+row)*K + k0 + 4*lkc);
            else
                wv[r] = make_float4(0.f,0.f,0.f,0.f);
        }
    };
    auto st_tile = [&](int buf) {
        #pragma unroll
        for (int r = 0; r < 2; r++) {
            int row = lm + 64*r;
            int base = row*16 + 4*(lkc ^ ((row>>1)&3));
            uint4 a4 = make_uint4(f2tf32(av[r].x), f2tf32(av[r].y),
                                  f2tf32(av[r].z), f2tf32(av[r].w));
            uint4 w4 = make_uint4(f2tf32(wv[r].x), f2tf32(wv[r].y),
                                  f2tf32(wv[r].z), f2tf32(wv[r].w));
            *(uint4*)&As[buf][base] = a4;
            *(uint4*)&Ws[buf][base] = w4;
        }
    };

    ld_tile(0);
    st_tile(0);
    __syncthreads();

    const int nk = K / 16;
    for (int it = 0; it < nk; it++) {
        int buf = it & 1;
        if (it + 1 < nk) ld_tile((it+1)*16);

        // compute on buf: two k8 chunks
        #pragma unroll
        for (int kc2 = 0; kc2 < 2; kc2++) {
            const int kb = kc2 * 8;
            uint32_t afrag[4][4];
            #pragma unroll
            for (int mi = 0; mi < 4; mi++) {
                int r0 = warp_m + mi*16 + (lane>>2);
                afrag[mi][0] = As[buf][swz_idx(r0,     kb + (lane&3))];
                afrag[mi][1] = As[buf][swz_idx(r0 + 8, kb + (lane&3))];
                afrag[mi][2] = As[buf][swz_idx(r0,     kb + 4 + (lane&3))];
                afrag[mi][3] = As[buf][swz_idx(r0 + 8, kb + 4 + (lane&3))];
            }
            uint32_t bfrag[4][2];
            #pragma unroll
            for (int ni = 0; ni < 4; ni++) {
                int nr = warp_n + ni*8 + (lane>>2);
                bfrag[ni][0] = Ws[buf][swz_idx(nr, kb + (lane&3))];
                bfrag[ni][1] = Ws[buf][swz_idx(nr, kb + 4 + (lane&3))];
            }
            #pragma unroll
            for (int mi = 0; mi < 4; mi++)
                #pragma unroll
                for (int ni = 0; ni < 4; ni++) {
                    asm volatile(
                        "mma.sync.aligned.m16n8k8.row.col.f32.tf32.tf32.f32 "
                        "{%0,%1,%2,%3}, {%4,%5,%6,%7}, {%8,%9}, {%0,%1,%2,%3};"
                        : "+f"(acc[mi][ni][0]), "+f"(acc[mi][ni][1]),
                          "+f"(acc[mi][ni][2]), "+f"(acc[mi][ni][3])
                        : "r"(afrag[mi][0]), "r"(afrag[mi][1]),
                          "r"(afrag[mi][2]), "r"(afrag[mi][3]),
                          "r"(bfrag[ni][0]), "r"(bfrag[ni][1]));
                }
        }

        if (it + 1 < nk) st_tile(buf ^ 1);
        __syncthreads();
    }

    // epilogue
    #pragma unroll
    for (int mi = 0; mi < 4; mi++) {
        #pragma unroll
        for (int ni = 0; ni < 4; ni++) {
            int row = m0 + warp_m + mi*16 + (lane>>2);
            int col = n0 + warp_n + ni*8 + 2*(lane&3);
            #pragma unroll
            for (int half = 0; half < 2; half++) {
                int r = row + half*8;
                float v0 = acc[mi][ni][half*2+0];
                float v1 = acc[mi][ni][half*2+1];
                if (EPI == 1) {
                    v0 += bias[col];   v1 += bias[col+1];
                    v0 = (v0 > 20.f) ? v0 : log1pf(__expf(v0));
                    v1 = (v1 > 20.f) ? v1 : log1pf(__expf(v1));
                } else if (EPI == 2) {
                    v0 = 1.f / (1.f + __expf(-v0));
                    v1 = 1.f / (1.f + __expf(-v1));
                }
                if (col + 1 < N) {
                    *(float2*)(C + (size_t)r*N + col) = make_float2(v0, v1);
                } else if (col < N) {
                    C[(size_t)r*N + col] = v0;
                }
            }
        }
    }
}

// ---------------- causal depthwise conv (k=4) + SiLU, float4 ----------------
__global__ void conv_silu_kernel(const float* __restrict__ w0, const float* __restrict__ w1,
                                 const float* __restrict__ cb0, const float* __restrict__ cb1) {
    int dir = blockIdx.z;
    const float* w  = dir ? w1 : w0;
    const float* cb = dir ? cb1 : cb0;
    int idx = blockIdx.x * blockDim.x + threadIdx.x;
    const int NC4 = DINNER/4;
    if (idx >= NROWS * NC4) return;
    int c4 = idx % NC4;
    int row = idx / NC4;
    int l = row & (SEQ-1);
    const float* base = g_xz[dir] + (size_t)row*XZN + c4*4;
    float4 x0  = *(const float4*)(base);
    float4 xm1 = (l>=1) ? *(const float4*)(base - 1*XZN) : make_float4(0,0,0,0);
    float4 xm2 = (l>=2) ? *(const float4*)(base - 2*XZN) : make_float4(0,0,0,0);
    float4 xm3 = (l>=3) ? *(const float4*)(base - 3*XZN) : make_float4(0,0,0,0);
    float4 cbv = ((const float4*)cb)[c4];
    float4 out;
    {
        float4 wv = ((const float4*)w)[c4*4+0];
        float a = cbv.x;
        a = fmaf(wv.x, xm3.x, a); a = fmaf(wv.y, xm2.x, a);
        a = fmaf(wv.z, xm1.x, a); a = fmaf(wv.w, x0.x, a);
        out.x = a / (1.f + __expf(-a));
    }
    {
        float4 wv = ((const float4*)w)[c4*4+1];
        float a = cbv.y;
        a = fmaf(wv.x, xm3.y, a); a = fmaf(wv.y, xm2.y, a);
        a = fmaf(wv.z, xm1.y, a); a = fmaf(wv.w, x0.y, a);
        out.y = a / (1.f + __expf(-a));
    }
    {
        float4 wv = ((const float4*)w)[c4*4+2];
        float a = cbv.z;
        a = fmaf(wv.x, xm3.z, a); a = fmaf(wv.y, xm2.z, a);
        a = fmaf(wv.z, xm1.z, a); a = fmaf(wv.w, x0.z, a);
        out.z = a / (1.f + __expf(-a));
    }
    {
        float4 wv = ((const float4*)w)[c4*4+3];
        float a = cbv.w;
        a = fmaf(wv.x, xm3.w, a); a = fmaf(wv.y, xm2.w, a);
        a = fmaf(wv.z, xm1.w, a); a = fmaf(wv.w, x0.w, a);
        out.w = a / (1.f + __expf(-a));
    }
    *(float4*)(g_xi[dir] + (size_t)row*DINNER + c4*4) = out;
}

// ---------------- selective scan (fused with gate + D skip) ----------------
__global__ __launch_bounds__(256)
void scan_kernel(const float* __restrict__ D0, const float* __restrict__ D1) {
    int dir = blockIdx.z;
    const float* Dp = dir ? D1 : D0;
    int d = blockIdx.x * blockDim.x + threadIdx.x;
    int b = blockIdx.y;
    int lane = threadIdx.x & 31;

    const float* dtp = g_dt[dir]  + (size_t)b*SEQ*DINNER + d;
    const float* xip = g_xi[dir]  + (size_t)b*SEQ*DINNER + d;
    const float* zp  = g_xz[dir]  + (size_t)b*SEQ*XZN + DINNER + d;
    const float* vp  = g_dbc[dir] + (size_t)b*SEQ*DBCN + 64 + lane;
    float* yp        = g_y[dir]   + (size_t)b*SEQ*DINNER + d;

    float h[DSTATE];
    #pragma unroll
    for (int s = 0; s < DSTATE; s++) h[s] = 0.f;
    float Av[DSTATE];
    #pragma unroll
    for (int s = 0; s < DSTATE; s++) Av[s] = g_A[dir][d*DSTATE + s];
    float Dv = Dp[d];
    int fast = g_fastA[dir];

    #pragma unroll 1
    for (int l0 = 0; l0 < SEQ; l0 += 4) {
        float cdt[4], cxi[4], cz[4], cv[4];
        #pragma unroll
        for (int u = 0; u < 4; u++) {
            int r = l0 + u;
            cdt[u] = dtp[(size_t)r*DINNER];
            cxi[u] = xip[(size_t)r*DINNER];
            cz[u]  = zp [(size_t)r*XZN];
            cv[u]  = vp [(size_t)r*DBCN];
        }
        #pragma unroll
        for (int u = 0; u < 4; u++) {
            float dt = cdt[u], xi = cxi[u], z = cz[u], v = cv[u];
            float dtxi = dt * xi;
            float acc = 0.f;
            if (fast) {
                float e = __expf(-dt);
                float p = 1.f;
                #pragma unroll
                for (int s = 0; s < DSTATE; s++) {
                    p *= e;
                    float bs = __shfl_sync(0xffffffffu, v, s);
                    float cs = __shfl_sync(0xffffffffu, v, 16 + s);
                    h[s] = fmaf(p, h[s], dtxi * bs);
                    acc = fmaf(h[s], cs, acc);
                }
            } else {
                #pragma unroll
                for (int s = 0; s < DSTATE; s++) {
                    float a = __expf(dt * Av[s]);
                    float bs = __shfl_sync(0xffffffffu, v, s);
                    float cs = __shfl_sync(0xffffffffu, v, 16 + s);
                    h[s] = fmaf(a, h[s], dtxi * bs);
                    acc = fmaf(h[s], cs, acc);
                }
            }
            float sz = z / (1.f + __expf(-z));
            yp[(size_t)(l0+u)*DINNER] = (acc + xi * Dv) * sz;
        }
    }
}

// ---------------- combine dirs + LayerNorm + residual ----------------------
__global__ __launch_bounds__(256)
void combine_ln_kernel(const float* __restrict__ x,
                       const float* __restrict__ lng, const float* __restrict__ lnb,
                       float* __restrict__ out) {
    int row = blockIdx.x;
    int b = row / SEQ, l = row % SEQ;
    const float* f  = g_outd[0] + (size_t)row*DMODEL;
    const float* bk = g_outd[1] + (size_t)(b*SEQ + (SEQ-1-l))*DMODEL;
    int tid = threadIdx.x;

    float vals[4];
    float s = 0.f, s2 = 0.f;
    #pragma unroll
    for (int j = 0; j < 4; j++) {
        int i = tid + j*256;
        float dv = 0.5f * (f[i] + bk[i]);
        vals[j] = dv;
        s += dv; s2 += dv*dv;
    }
    #pragma unroll
    for (int o = 16; o; o >>= 1) {
        s  += __shfl_xor_sync(0xffffffffu, s,  o);
        s2 += __shfl_xor_sync(0xffffffffu, s2, o);
    }
    __shared__ float sh[2][8];
    if ((tid & 31) == 0) { sh[0][tid>>5] = s; sh[1][tid>>5] = s2; }
    __syncthreads();
    if (tid < 32) {
        float a  = (tid < 8) ? sh[0][tid] : 0.f;
        float a2 = (tid < 8) ? sh[1][tid] : 0.f;
        #pragma unroll
        for (int o = 4; o; o >>= 1) {
            a  += __shfl_xor_sync(0xffffffffu, a,  o);
            a2 += __shfl_xor_sync(0xffffffffu, a2, o);
        }
        if (tid == 0) { sh[0][0] = a; sh[1][0] = a2; }
    }
    __syncthreads();
    float mu  = sh[0][0] * (1.f/DMODEL);
    float var = sh[1][0] * (1.f/DMODEL) - mu*mu;
    float rstd = rsqrtf(var + 1e-5f);
    #pragma unroll
    for (int j = 0; j < 4; j++) {
        int i = tid + j*256;
        out[(size_t)row*DMODEL + i] =
            (vals[j] - mu) * rstd * lng[i] + lnb[i] + x[(size_t)row*DMODEL + i];
    }
}

// ---------------- host launcher --------------------------------------------
extern "C" void kernel_launch(void* const* d_in, const int* in_sizes, int n_in,
                              void* d_out, int out_size) {
    (void)in_sizes; (void)n_in; (void)out_size;
    const float* x       = (const float*)d_in[0];
    const float* Win[2]  = {(const float*)d_in[1],  (const float*)d_in[10]};
    const float* cw[2]   = {(const float*)d_in[2],  (const float*)d_in[11]};
    const float* cbv[2]  = {(const float*)d_in[3],  (const float*)d_in[12]};
    const float* xproj[2]= {(const float*)d_in[4],  (const float*)d_in[13]};
    const float* dtw[2]  = {(const float*)d_in[5],  (const float*)d_in[14]};
    const float* dtb[2]  = {(const float*)d_in[6],  (const float*)d_in[15]};
    const float* Alog[2] = {(const float*)d_in[7],  (const float*)d_in[16]};
    const float* Dp[2]   = {(const float*)d_in[8],  (const float*)d_in[17]};
    const float* Wout[2] = {(const float*)d_in[9],  (const float*)d_in[18]};
    const float* lng = (const float*)d_in[19];
    const float* lnb = (const float*)d_in[20];
    float* out = (float*)d_out;

    float *p_xrev, *p_xz, *p_xi, *p_dbc, *p_dt, *p_y, *p_out;
    cudaGetSymbolAddress((void**)&p_xrev, g_xrev);
    cudaGetSymbolAddress((void**)&p_xz,   g_xz);
    cudaGetSymbolAddress((void**)&p_xi,   g_xi);
    cudaGetSymbolAddress((void**)&p_dbc,  g_dbc);
    cudaGetSymbolAddress((void**)&p_dt,   g_dt);
    cudaGetSymbolAddress((void**)&p_y,    g_y);
    cudaGetSymbolAddress((void**)&p_out,  g_outd);

    const size_t sXZ  = (size_t)NROWS*XZN;
    const size_t sIN  = (size_t)NROWS*DINNER;
    const size_t sDBC = (size_t)NROWS*DBCN;
    const size_t sMD  = (size_t)NROWS*DMODEL;

    reverse_kernel<<<(NROWS*DMODEL + 255)/256, 256>>>(x);
    prepA_kernel<<<2, 256>>>(Alog[0], Alog[1]);

    // in_proj: xz = x @ Win^T   (M=2048, N=4096, K=1024)
    mma_gemm<0><<<dim3(XZN/128, NROWS/128, 2), 256>>>(
        x, p_xrev, Win[0], Win[1], nullptr, nullptr,
        p_xz, p_xz + sXZ, NROWS, XZN, DMODEL, DMODEL);

    // conv + silu
    conv_silu_kernel<<<dim3((NROWS*(DINNER/4) + 255)/256, 1, 2), 256>>>(
        cw[0], cw[1], cbv[0], cbv[1]);

    // x_proj: dbc = xi @ xproj^T   (M=2048, N=96, K=2048)
    mma_gemm<0><<<dim3(1, NROWS/128, 2), 256>>>(
        p_xi, p_xi + sIN, xproj[0], xproj[1], nullptr, nullptr,
        p_dbc, p_dbc + sDBC, NROWS, DBCN, DINNER, DINNER);

    // dt = softplus(dbc[:, :64] @ dtw^T + dtb)   (M=2048, N=2048, K=64, lda=96)
    mma_gemm<1><<<dim3(DINNER/128, NROWS/128, 2), 256>>>(
        p_dbc, p_dbc + sDBC, dtw[0], dtw[1], dtb[0], dtb[1],
        p_dt, p_dt + sIN, NROWS, DINNER, 64, DBCN);

    // selective scan + gating -> y
    scan_kernel<<<dim3(DINNER/256, BATCH, 2), 256>>>(Dp[0], Dp[1]);

    // out = sigmoid(y @ Wout^T)   (M=2048, N=1024, K=2048)
    mma_gemm<2><<<dim3(DMODEL/128, NROWS/128, 2), 256>>>(
        p_y, p_y + sIN, Wout[0], Wout[1], nullptr, nullptr,
        p_out, p_out + sMD, NROWS, DMODEL, DINNER, DINNER);

    // combine + LN + residual
    combine_ln_kernel<<<NROWS, 256>>>(x, lng, lnb, out);
}

// round 4
// speedup vs baseline: 2.6897x; 1.2624x over previous
#include <cuda_runtime.h>
#include <math.h>
#include <stdint.h>

#define BATCH  2
#define SEQ    1024
#define DMODEL 1024
#define DINNER 2048
#define DSTATE 16
#define NROWS  (BATCH*SEQ)      // 2048
#define DBCN   96
#define XZN    (2*DINNER)       // 4096
#define NSPLIT 8                // split-K factor for x_proj

// ---------------- scratch ---------------------------------------------------
__device__ float g_xrev[(size_t)NROWS*DMODEL];
__device__ float g_xz  [2][(size_t)NROWS*XZN];
__device__ float g_xi  [2][(size_t)NROWS*DINNER];
__device__ float g_dbc [2][(size_t)NROWS*DBCN];
__device__ float g_dbcp[2][NSPLIT][(size_t)NROWS*DBCN];
__device__ float g_dt  [2][(size_t)NROWS*DINNER];
__device__ float g_y   [2][(size_t)NROWS*DINNER];
__device__ float g_outd[2][(size_t)NROWS*DMODEL];
__device__ float g_A   [2][DINNER*DSTATE];
__device__ int   g_fastA[2];

// ---------------- helpers ---------------------------------------------------
__device__ __forceinline__ uint32_t smem_u32(const void* p) {
    uint32_t a;
    asm("{ .reg .u64 t; cvta.to.shared.u64 t, %1; cvt.u32.u64 %0, t; }"
        : "=r"(a) : "l"(p));
    return a;
}
__device__ __forceinline__ uint32_t f2tf32(float f) {
    uint32_t r;
    asm("cvt.rna.tf32.f32 %0, %1;" : "=r"(r) : "f"(f));
    return r;
}
__device__ __forceinline__ void cp16(uint32_t dst, const void* src, int sz) {
    asm volatile("cp.async.cg.shared.global [%0], [%1], 16, %2;"
                 :: "r"(dst), "l"(src), "r"(sz) : "memory");
}
__device__ __forceinline__ void cp_commit() {
    asm volatile("cp.async.commit_group;" ::: "memory");
}
__device__ __forceinline__ void cp_wait1() {
    asm volatile("cp.async.wait_group 1;" ::: "memory");
}

// ---------------- misc kernels ---------------------------------------------
__global__ void reverse_kernel(const float* __restrict__ x) {
    int idx = blockIdx.x * blockDim.x + threadIdx.x;
    if (idx >= NROWS * DMODEL) return;
    int c = idx % DMODEL;
    int row = idx / DMODEL;
    int b = row / SEQ, l = row % SEQ;
    g_xrev[(size_t)(b*SEQ + (SEQ-1-l))*DMODEL + c] = x[idx];
}

__global__ void prepA_kernel(const float* __restrict__ Alog0,
                             const float* __restrict__ Alog1) {
    int dir = blockIdx.x;
    const float* Alog = dir ? Alog1 : Alog0;
    __shared__ int ok;
    if (threadIdx.x == 0) ok = 1;
    __syncthreads();
    bool good = true;
    for (int i = threadIdx.x; i < DINNER*DSTATE; i += blockDim.x) {
        float a = -__expf(Alog[i]);
        g_A[dir][i] = a;
        int s = i & (DSTATE-1);
        if (fabsf(a + (float)(s+1)) > 1e-3f * (float)(s+1)) good = false;
    }
    if (!good) atomicExch(&ok, 0);
    __syncthreads();
    if (threadIdx.x == 0) g_fastA[dir] = ok;
}

// ==============  TF32 mma.sync GEMM, cp.async 3-stage pipeline  =============
// C(2048, Ntot) = A(2048, K; lda) * W(N, K; ldw)^T   (per-direction, per-split)
// Block tile 128x128, BK=16, 256 thr (8 warps at 64x32). 3-stage cp.async.
// SMEM layout per tile: raw fp32, idx f(row,k)=row*16+4*((k>>2)^((row>>1)&3))+(k&3)
// EPI: 0 none, 1 softplus(v+bias[n]), 2 sigmoid(v)

#define STG 16384               // bytes per stage (A 8KB + B 8KB)

template<int EPI>
__global__ __launch_bounds__(256, 2)
void mma_gemm2(const float* __restrict__ A0, const float* __restrict__ A1,
               const float* __restrict__ W0, const float* __restrict__ W1,
               const float* __restrict__ b0, const float* __restrict__ b1,
               float* __restrict__ C0, float* __restrict__ C1,
               int N, int Ntot, int Ksub, int lda, int ldw,
               int nsplit, size_t csplit) {
    const int dir   = blockIdx.z / nsplit;
    const int split = blockIdx.z - dir*nsplit;
    const float* A = dir ? A1 : A0;
    const float* W = dir ? W1 : W0;
    const float* bias = dir ? b1 : b0;
    float* C = (dir ? C1 : C0) + (size_t)split * csplit;
    const int koff = split * Ksub;

    __shared__ __align__(16) char sm[3*STG];
    const uint32_t sbase = smem_u32(sm);

    const int tid  = threadIdx.x;
    const int lane = tid & 31;
    const int wid  = tid >> 5;
    const int warp_m = (wid & 1) * 64;
    const int warp_n = (wid >> 1) * 32;
    const int m0 = blockIdx.y * 128;
    const int n0 = blockIdx.x * 128;

    // loader constants: idx in [0,512): row=idx>>2 (0..127), kc=idx&3
    const int lrow = tid >> 2;            // rows handled: lrow, lrow+64
    const int lkc  = tid & 3;

    // fragment address constants (see derivation: xor nibble uniform per thread)
    const int lq = lane & 3;
    const int kx = (lane >> 3) & 3;
    int ko[4];
    #pragma unroll
    for (int c = 0; c < 4; c++) ko[c] = 4*(c ^ kx);
    int abase[4], bbase[4];
    #pragma unroll
    for (int mi = 0; mi < 4; mi++)
        abase[mi] = (warp_m + mi*16 + (lane>>2))*16 + lq;
    #pragma unroll
    for (int ni = 0; ni < 4; ni++)
        bbase[ni] = (warp_n + ni*8 + (lane>>2))*16 + lq;

    float acc[4][4][4];
    #pragma unroll
    for (int i = 0; i < 4; i++)
        #pragma unroll
        for (int j = 0; j < 4; j++)
            #pragma unroll
            for (int r = 0; r < 4; r++) acc[i][j][r] = 0.f;

    const int nk = Ksub / 16;

    auto stage_load = [&](int it) {
        int st = it % 3;
        uint32_t sA = sbase + st*STG;
        uint32_t sB = sA + 8192;
        int k0 = koff + it*16;
        #pragma unroll
        for (int j = 0; j < 2; j++) {
            int row = lrow + j*64;
            uint32_t d = sA + row*64 + 16*(lkc ^ ((row>>1)&3));
            const float* s = A + (size_t)(m0+row)*lda + k0 + lkc*4;
            cp16(d, s, 16);
        }
        #pragma unroll
        for (int j = 0; j < 2; j++) {
            int row = lrow + j*64;
            int wr = n0 + row;
            int valid = (wr < N);
            uint32_t d = sB + row*64 + 16*(lkc ^ ((row>>1)&3));
            const float* s = W + (size_t)(valid ? wr : 0)*ldw + k0 + lkc*4;
            cp16(d, s, valid ? 16 : 0);
        }
        cp_commit();
    };

    stage_load(0);
    stage_load(1);

    for (int it = 0; it < nk; it++) {
        cp_wait1();
        __syncthreads();
        if (it + 2 < nk) stage_load(it + 2); else cp_commit();

        int st = it % 3;
        const uint32_t* Sa = (const uint32_t*)(sm + st*STG);
        const uint32_t* Sw = (const uint32_t*)(sm + st*STG + 8192);

        #pragma unroll
        for (int kc2 = 0; kc2 < 2; kc2++) {
            const int o0 = ko[kc2*2], o1 = ko[kc2*2+1];
            uint32_t afrag[4][4];
            #pragma unroll
            for (int mi = 0; mi < 4; mi++) {
                afrag[mi][0] = f2tf32(__uint_as_float(Sa[abase[mi] + o0]));
                afrag[mi][1] = f2tf32(__uint_as_float(Sa[abase[mi] + 128 + o0]));
                afrag[mi][2] = f2tf32(__uint_as_float(Sa[abase[mi] + o1]));
                afrag[mi][3] = f2tf32(__uint_as_float(Sa[abase[mi] + 128 + o1]));
            }
            uint32_t bfrag[4][2];
            #pragma unroll
            for (int ni = 0; ni < 4; ni++) {
                bfrag[ni][0] = f2tf32(__uint_as_float(Sw[bbase[ni] + o0]));
                bfrag[ni][1] = f2tf32(__uint_as_float(Sw[bbase[ni] + o1]));
            }
            #pragma unroll
            for (int mi = 0; mi < 4; mi++)
                #pragma unroll
                for (int ni = 0; ni < 4; ni++) {
                    asm volatile(
                        "mma.sync.aligned.m16n8k8.row.col.f32.tf32.tf32.f32 "
                        "{%0,%1,%2,%3}, {%4,%5,%6,%7}, {%8,%9}, {%0,%1,%2,%3};"
                        : "+f"(acc[mi][ni][0]), "+f"(acc[mi][ni][1]),
                          "+f"(acc[mi][ni][2]), "+f"(acc[mi][ni][3])
                        : "r"(afrag[mi][0]), "r"(afrag[mi][1]),
                          "r"(afrag[mi][2]), "r"(afrag[mi][3]),
                          "r"(bfrag[ni][0]), "r"(bfrag[ni][1]));
                }
        }
        __syncthreads();
    }

    // epilogue
    #pragma unroll
    for (int mi = 0; mi < 4; mi++) {
        #pragma unroll
        for (int ni = 0; ni < 4; ni++) {
            int row = m0 + warp_m + mi*16 + (lane>>2);
            int col = n0 + warp_n + ni*8 + 2*(lane&3);
            #pragma unroll
            for (int half = 0; half < 2; half++) {
                int r = row + half*8;
                float v0 = acc[mi][ni][half*2+0];
                float v1 = acc[mi][ni][half*2+1];
                if (EPI == 1) {
                    v0 += bias[col];   v1 += bias[col+1];
                    v0 = (v0 > 20.f) ? v0 : log1pf(__expf(v0));
                    v1 = (v1 > 20.f) ? v1 : log1pf(__expf(v1));
                } else if (EPI == 2) {
                    v0 = 1.f / (1.f + __expf(-v0));
                    v1 = 1.f / (1.f + __expf(-v1));
                }
                if (col + 1 < N)
                    *(float2*)(C + (size_t)r*Ntot + col) = make_float2(v0, v1);
            }
        }
    }
}

// ---------------- split-K reduce for x_proj --------------------------------
__global__ void reduce_dbc_kernel() {
    int idx = blockIdx.x * blockDim.x + threadIdx.x;
    const int TOT = NROWS*DBCN;
    if (idx >= 2*TOT) return;
    int dir = idx / TOT;
    int e = idx - dir*TOT;
    float s = 0.f;
    #pragma unroll
    for (int p = 0; p < NSPLIT; p++) s += g_dbcp[dir][p][e];
    g_dbc[dir][e] = s;
}

// ---------------- causal depthwise conv (k=4) + SiLU, float4 ----------------
__global__ void conv_silu_kernel(const float* __restrict__ w0, const float* __restrict__ w1,
                                 const float* __restrict__ cb0, const float* __restrict__ cb1) {
    int dir = blockIdx.z;
    const float* w  = dir ? w1 : w0;
    const float* cb = dir ? cb1 : cb0;
    int idx = blockIdx.x * blockDim.x + threadIdx.x;
    const int NC4 = DINNER/4;
    if (idx >= NROWS * NC4) return;
    int c4 = idx % NC4;
    int row = idx / NC4;
    int l = row & (SEQ-1);
    const float* base = g_xz[dir] + (size_t)row*XZN + c4*4;
    float4 x0  = *(const float4*)(base);
    float4 xm1 = (l>=1) ? *(const float4*)(base - 1*XZN) : make_float4(0,0,0,0);
    float4 xm2 = (l>=2) ? *(const float4*)(base - 2*XZN) : make_float4(0,0,0,0);
    float4 xm3 = (l>=3) ? *(const float4*)(base - 3*XZN) : make_float4(0,0,0,0);
    float4 cbv = ((const float4*)cb)[c4];
    float4 out;
    {
        float4 wv = ((const float4*)w)[c4*4+0];
        float a = cbv.x;
        a = fmaf(wv.x, xm3.x, a); a = fmaf(wv.y, xm2.x, a);
        a = fmaf(wv.z, xm1.x, a); a = fmaf(wv.w, x0.x, a);
        out.x = a / (1.f + __expf(-a));
    }
    {
        float4 wv = ((const float4*)w)[c4*4+1];
        float a = cbv.y;
        a = fmaf(wv.x, xm3.y, a); a = fmaf(wv.y, xm2.y, a);
        a = fmaf(wv.z, xm1.y, a); a = fmaf(wv.w, x0.y, a);
        out.y = a / (1.f + __expf(-a));
    }
    {
        float4 wv = ((const float4*)w)[c4*4+2];
        float a = cbv.z;
        a = fmaf(wv.x, xm3.z, a); a = fmaf(wv.y, xm2.z, a);
        a = fmaf(wv.z, xm1.z, a); a = fmaf(wv.w, x0.z, a);
        out.z = a / (1.f + __expf(-a));
    }
    {
        float4 wv = ((const float4*)w)[c4*4+3];
        float a = cbv.w;
        a = fmaf(wv.x, xm3.w, a); a = fmaf(wv.y, xm2.w, a);
        a = fmaf(wv.z, xm1.w, a); a = fmaf(wv.w, x0.w, a);
        out.w = a / (1.f + __expf(-a));
    }
    *(float4*)(g_xi[dir] + (size_t)row*DINNER + c4*4) = out;
}

// ---------------- selective scan -------------------------------------------
__global__ __launch_bounds__(256)
void scan_kernel(const float* __restrict__ D0, const float* __restrict__ D1) {
    int dir = blockIdx.z;
    const float* Dp = dir ? D1 : D0;
    int d = blockIdx.x * blockDim.x + threadIdx.x;
    int b = blockIdx.y;
    int lane = threadIdx.x & 31;

    const float* dtp = g_dt[dir]  + (size_t)b*SEQ*DINNER + d;
    const float* xip = g_xi[dir]  + (size_t)b*SEQ*DINNER + d;
    const float* zp  = g_xz[dir]  + (size_t)b*SEQ*XZN + DINNER + d;
    const float* vp  = g_dbc[dir] + (size_t)b*SEQ*DBCN + 64 + lane;
    float* yp        = g_y[dir]   + (size_t)b*SEQ*DINNER + d;

    float h[DSTATE];
    #pragma unroll
    for (int s = 0; s < DSTATE; s++) h[s] = 0.f;
    float Av[DSTATE];
    #pragma unroll
    for (int s = 0; s < DSTATE; s++) Av[s] = g_A[dir][d*DSTATE + s];
    float Dv = Dp[d];
    int fast = g_fastA[dir];

    #pragma unroll 1
    for (int l0 = 0; l0 < SEQ; l0 += 4) {
        float cdt[4], cxi[4], cz[4], cv[4];
        #pragma unroll
        for (int u = 0; u < 4; u++) {
            int r = l0 + u;
            cdt[u] = dtp[(size_t)r*DINNER];
            cxi[u] = xip[(size_t)r*DINNER];
            cz[u]  = zp [(size_t)r*XZN];
            cv[u]  = vp [(size_t)r*DBCN];
        }
        #pragma unroll
        for (int u = 0; u < 4; u++) {
            float dt = cdt[u], xi = cxi[u], z = cz[u], v = cv[u];
            float dtxi = dt * xi;
            float acc = 0.f;
            if (fast) {
                float e = __expf(-dt);
                float p = 1.f;
                #pragma unroll
                for (int s = 0; s < DSTATE; s++) {
                    p *= e;
                    float bs = __shfl_sync(0xffffffffu, v, s);
                    float cs = __shfl_sync(0xffffffffu, v, 16 + s);
                    h[s] = fmaf(p, h[s], dtxi * bs);
                    acc = fmaf(h[s], cs, acc);
                }
            } else {
                #pragma unroll
                for (int s = 0; s < DSTATE; s++) {
                    float a = __expf(dt * Av[s]);
                    float bs = __shfl_sync(0xffffffffu, v, s);
                    float cs = __shfl_sync(0xffffffffu, v, 16 + s);
                    h[s] = fmaf(a, h[s], dtxi * bs);
                    acc = fmaf(h[s], cs, acc);
                }
            }
            float sz = z / (1.f + __expf(-z));
            yp[(size_t)(l0+u)*DINNER] = (acc + xi * Dv) * sz;
        }
    }
}

// ---------------- combine dirs + LayerNorm + residual ----------------------
__global__ __launch_bounds__(256)
void combine_ln_kernel(const float* __restrict__ x,
                       const float* __restrict__ lng, const float* __restrict__ lnb,
                       float* __restrict__ out) {
    int row = blockIdx.x;
    int b = row / SEQ, l = row % SEQ;
    const float* f  = g_outd[0] + (size_t)row*DMODEL;
    const float* bk = g_outd[1] + (size_t)(b*SEQ + (SEQ-1-l))*DMODEL;
    int tid = threadIdx.x;

    float vals[4];
    float s = 0.f, s2 = 0.f;
    #pragma unroll
    for (int j = 0; j < 4; j++) {
        int i = tid + j*256;
        float dv = 0.5f * (f[i] + bk[i]);
        vals[j] = dv;
        s += dv; s2 += dv*dv;
    }
    #pragma unroll
    for (int o = 16; o; o >>= 1) {
        s  += __shfl_xor_sync(0xffffffffu, s,  o);
        s2 += __shfl_xor_sync(0xffffffffu, s2, o);
    }
    __shared__ float sh[2][8];
    if ((tid & 31) == 0) { sh[0][tid>>5] = s; sh[1][tid>>5] = s2; }
    __syncthreads();
    if (tid < 32) {
        float a  = (tid < 8) ? sh[0][tid] : 0.f;
        float a2 = (tid < 8) ? sh[1][tid] : 0.f;
        #pragma unroll
        for (int o = 4; o; o >>= 1) {
            a  += __shfl_xor_sync(0xffffffffu, a,  o);
            a2 += __shfl_xor_sync(0xffffffffu, a2, o);
        }
        if (tid == 0) { sh[0][0] = a; sh[1][0] = a2; }
    }
    __syncthreads();
    float mu  = sh[0][0] * (1.f/DMODEL);
    float var = sh[1][0] * (1.f/DMODEL) - mu*mu;
    float rstd = rsqrtf(var + 1e-5f);
    #pragma unroll
    for (int j = 0; j < 4; j++) {
        int i = tid + j*256;
        out[(size_t)row*DMODEL + i] =
            (vals[j] - mu) * rstd * lng[i] + lnb[i] + x[(size_t)row*DMODEL + i];
    }
}

// ---------------- host launcher --------------------------------------------
extern "C" void kernel_launch(void* const* d_in, const int* in_sizes, int n_in,
                              void* d_out, int out_size) {
    (void)in_sizes; (void)n_in; (void)out_size;
    const float* x       = (const float*)d_in[0];
    const float* Win[2]  = {(const float*)d_in[1],  (const float*)d_in[10]};
    const float* cw[2]   = {(const float*)d_in[2],  (const float*)d_in[11]};
    const float* cbv[2]  = {(const float*)d_in[3],  (const float*)d_in[12]};
    const float* xproj[2]= {(const float*)d_in[4],  (const float*)d_in[13]};
    const float* dtw[2]  = {(const float*)d_in[5],  (const float*)d_in[14]};
    const float* dtb[2]  = {(const float*)d_in[6],  (const float*)d_in[15]};
    const float* Alog[2] = {(const float*)d_in[7],  (const float*)d_in[16]};
    const float* Dp[2]   = {(const float*)d_in[8],  (const float*)d_in[17]};
    const float* Wout[2] = {(const float*)d_in[9],  (const float*)d_in[18]};
    const float* lng = (const float*)d_in[19];
    const float* lnb = (const float*)d_in[20];
    float* out = (float*)d_out;

    float *p_xrev, *p_xz, *p_xi, *p_dbc, *p_dbcp, *p_dt, *p_y, *p_out;
    cudaGetSymbolAddress((void**)&p_xrev, g_xrev);
    cudaGetSymbolAddress((void**)&p_xz,   g_xz);
    cudaGetSymbolAddress((void**)&p_xi,   g_xi);
    cudaGetSymbolAddress((void**)&p_dbc,  g_dbc);
    cudaGetSymbolAddress((void**)&p_dbcp, g_dbcp);
    cudaGetSymbolAddress((void**)&p_dt,   g_dt);
    cudaGetSymbolAddress((void**)&p_y,    g_y);
    cudaGetSymbolAddress((void**)&p_out,  g_outd);

    const size_t sXZ  = (size_t)NROWS*XZN;
    const size_t sIN  = (size_t)NROWS*DINNER;
    const size_t sDBC = (size_t)NROWS*DBCN;
    const size_t sMD  = (size_t)NROWS*DMODEL;

    reverse_kernel<<<(NROWS*DMODEL + 255)/256, 256>>>(x);
    prepA_kernel<<<2, 256>>>(Alog[0], Alog[1]);

    // in_proj: xz = x @ Win^T   (N=4096, K=1024)
    mma_gemm2<0><<<dim3(XZN/128, NROWS/128, 2), 256>>>(
        x, p_xrev, Win[0], Win[1], nullptr, nullptr,
        p_xz, p_xz + sXZ, XZN, XZN, DMODEL, DMODEL, DMODEL, 1, 0);

    conv_silu_kernel<<<dim3((NROWS*(DINNER/4) + 255)/256, 1, 2), 256>>>(
        cw[0], cw[1], cbv[0], cbv[1]);

    // x_proj split-K: dbc_part = xi @ xproj^T  (N=96, K=2048/8 per split)
    mma_gemm2<0><<<dim3(1, NROWS/128, 2*NSPLIT), 256>>>(
        p_xi, p_xi + sIN, xproj[0], xproj[1], nullptr, nullptr,
        p_dbcp, p_dbcp + NSPLIT*sDBC, DBCN, DBCN, DINNER/NSPLIT, DINNER, DINNER,
        NSPLIT, sDBC);
    reduce_dbc_kernel<<<(2*NROWS*DBCN + 255)/256, 256>>>();

    // dt = softplus(dbc[:, :64] @ dtw^T + dtb)  (N=2048, K=64, lda=96)
    mma_gemm2<1><<<dim3(DINNER/128, NROWS/128, 2), 256>>>(
        p_dbc, p_dbc + sDBC, dtw[0], dtw[1], dtb[0], dtb[1],
        p_dt, p_dt + sIN, DINNER, DINNER, 64, DBCN, 64, 1, 0);

    scan_kernel<<<dim3(DINNER/256, BATCH, 2), 256>>>(Dp[0], Dp[1]);

    // out = sigmoid(y @ Wout^T)  (N=1024, K=2048)
    mma_gemm2<2><<<dim3(DMODEL/128, NROWS/128, 2), 256>>>(
        p_y, p_y + sIN, Wout[0], Wout[1], nullptr, nullptr,
        p_out, p_out + sMD, DMODEL, DMODEL, DINNER, DINNER, DINNER, 1, 0);

    combine_ln_kernel<<<NROWS, 256>>>(x, lng, lnb, out);
}